// round 3
// baseline (speedup 1.0000x reference)
#include <cuda_runtime.h>
#include <math_constants.h>

#define H 1024
#define S 32768
#define ROWS_PER_BLK 32
#define NBLK_SCORES (S / ROWS_PER_BLK)   // 1024 blocks, 1024 threads each
#define D_SLICES 64                      // 16 d-rows per slice
#define NORM_BLKS 128

// Scratch (no allocations allowed)
__device__ float g_vpart[D_SLICES * H];
__device__ float g_v[H];
__device__ float g_scores[S];
__device__ float g_bmax[NBLK_SCORES];
__device__ float g_bsum[NBLK_SCORES];

// ---------------------------------------------------------------------------
// K1: partial v[h] = sum over a 16-wide slice of d of W[d][h] * hidden[d]
// grid (H/256=4, D_SLICES=64), block 256. Coalesced reads of W rows.
// ---------------------------------------------------------------------------
__global__ void v_partial_kernel(const float* __restrict__ W,
                                 const float* __restrict__ hidden) {
    const int h  = blockIdx.x * 256 + threadIdx.x;
    const int d0 = blockIdx.y * (H / D_SLICES);
    float acc = 0.f;
#pragma unroll
    for (int dd = 0; dd < H / D_SLICES; dd++) {
        acc += W[(size_t)(d0 + dd) * H + h] * __ldg(&hidden[d0 + dd]);
    }
    g_vpart[blockIdx.y * H + h] = acc;
}

// ---------------------------------------------------------------------------
// K2: reduce partials -> g_v.  grid 4, block 256.
// (bias b dropped: softmax is shift-invariant, b.hidden is a constant)
// ---------------------------------------------------------------------------
__global__ void v_reduce_kernel() {
    const int h = blockIdx.x * 256 + threadIdx.x;
    float acc = 0.f;
#pragma unroll
    for (int i = 0; i < D_SLICES; i++) acc += g_vpart[i * H + h];
    g_v[h] = acc;
}

// ---------------------------------------------------------------------------
// K3: scores[s] = enc[s] . v     (the 128 MB streaming kernel)
// One warp per row; 32 rows per 1024-thread block. float4 loads.
// Emits per-block max m_b and per-block expsum S_b = sum exp(s - m_b).
// ---------------------------------------------------------------------------
__global__ __launch_bounds__(1024) void scores_kernel(const float* __restrict__ enc) {
    __shared__ float sv[H];
    __shared__ float s_sc[ROWS_PER_BLK];

    // stage v into shared (first 256 threads x float4)
    if (threadIdx.x < 256)
        reinterpret_cast<float4*>(sv)[threadIdx.x] =
            reinterpret_cast<const float4*>(g_v)[threadIdx.x];
    __syncthreads();

    const int warp = threadIdx.x >> 5;
    const int lane = threadIdx.x & 31;
    const size_t row = (size_t)blockIdx.x * ROWS_PER_BLK + warp;

    const float4* r  = reinterpret_cast<const float4*>(enc + row * H);
    const float4* v4 = reinterpret_cast<const float4*>(sv);

    float acc = 0.f;
#pragma unroll
    for (int k = 0; k < 8; k++) {
        float4 e  = r[lane + k * 32];
        float4 vv = v4[lane + k * 32];
        acc += e.x * vv.x + e.y * vv.y + e.z * vv.z + e.w * vv.w;
    }
#pragma unroll
    for (int o = 16; o > 0; o >>= 1) acc += __shfl_xor_sync(0xFFFFFFFFu, acc, o);

    if (lane == 0) {
        g_scores[row] = acc;
        s_sc[warp] = acc;
    }
    __syncthreads();

    // warp 0 reduces the 32 row-scores into (max, expsum)
    if (warp == 0) {
        float v = s_sc[lane];
        float m = v;
#pragma unroll
        for (int o = 16; o > 0; o >>= 1) m = fmaxf(m, __shfl_xor_sync(0xFFFFFFFFu, m, o));
        float e = __expf(v - m);
#pragma unroll
        for (int o = 16; o > 0; o >>= 1) e += __shfl_xor_sync(0xFFFFFFFFu, e, o);
        if (lane == 0) {
            g_bmax[blockIdx.x] = m;
            g_bsum[blockIdx.x] = e;
        }
    }
}

// ---------------------------------------------------------------------------
// K4: normalize with redundant per-block reduction of the 1024 (m,S) pairs.
// grid 128, block 256. Each block computes M and inv itself (8 KB from L2),
// then writes its 256-element slice of the output.
// ---------------------------------------------------------------------------
__global__ __launch_bounds__(256) void normalize_kernel(float* __restrict__ out) {
    __shared__ float red[256];
    const int tid = threadIdx.x;

    // redundant reduction over NBLK_SCORES pairs
    float pm[NBLK_SCORES / 256];
    float ps[NBLK_SCORES / 256];
    float m = -CUDART_INF_F;
#pragma unroll
    for (int k = 0; k < NBLK_SCORES / 256; k++) {
        pm[k] = g_bmax[tid + k * 256];
        ps[k] = g_bsum[tid + k * 256];
        m = fmaxf(m, pm[k]);
    }
    red[tid] = m;
    __syncthreads();
#pragma unroll
    for (int s = 128; s > 0; s >>= 1) {
        if (tid < s) red[tid] = fmaxf(red[tid], red[tid + s]);
        __syncthreads();
    }
    const float M = red[0];
    __syncthreads();

    float sum = 0.f;
#pragma unroll
    for (int k = 0; k < NBLK_SCORES / 256; k++)
        sum += ps[k] * __expf(pm[k] - M);
    red[tid] = sum;
    __syncthreads();
#pragma unroll
    for (int s = 128; s > 0; s >>= 1) {
        if (tid < s) red[tid] += red[tid + s];
        __syncthreads();
    }
    const float inv = 1.0f / red[0];

    const int i = blockIdx.x * 256 + tid;
    out[i] = __expf(g_scores[i] - M) * inv;
}

// ---------------------------------------------------------------------------
extern "C" void kernel_launch(void* const* d_in, const int* in_sizes, int n_in,
                              void* d_out, int out_size) {
    const float* hidden = (const float*)d_in[0];   // [H]
    const float* enc    = (const float*)d_in[1];   // [S, H]
    const float* W      = (const float*)d_in[2];   // [H, H]
    float* out          = (float*)d_out;           // [S]

    v_partial_kernel<<<dim3(H / 256, D_SLICES), 256>>>(W, hidden);
    v_reduce_kernel<<<H / 256, 256>>>();
    scores_kernel<<<NBLK_SCORES, 1024>>>(enc);
    normalize_kernel<<<NORM_BLKS, 256>>>(out);
}